// round 5
// baseline (speedup 1.0000x reference)
#include <cuda_runtime.h>
#include <cuda_bf16.h>
#include <cstdint>

// ---------------- problem constants ----------------
#define DD   1024
#define EE   8
#define HH   2048
#define NN   8192   // B*T tokens

// GEMM tile config: CTA 128x256, warp 64x64 (2M x 4N warps), K-chunk 32
#define TM   128
#define TN   256
#define TK   32
#define STAGES 4
#define A_LO 8192
#define B_HI 16384
#define B_LO 32768
#define STAGE_BYTES 49152            // Ahi8K + Alo8K + Bhi16K + Blo16K
#define SMEM_BYTES  (STAGES*STAGE_BYTES)   // 192 KB

// ---------------- static device scratch ----------------
__device__ int   g_cnt[EE];
__device__ int   g_tok[EE * NN];
__device__ float g_gate[EE * NN];
__device__ __nv_bfloat16 g_xg_hi[(size_t)EE * NN * DD];
__device__ __nv_bfloat16 g_xg_lo[(size_t)EE * NN * DD];
__device__ __nv_bfloat16 g_h_hi [(size_t)EE * NN * HH];
__device__ __nv_bfloat16 g_h_lo [(size_t)EE * NN * HH];
__device__ __nv_bfloat16 g_w1t_hi[(size_t)EE * DD * HH];
__device__ __nv_bfloat16 g_w1t_lo[(size_t)EE * DD * HH];
__device__ __nv_bfloat16 g_w2t_hi[(size_t)EE * HH * DD];
__device__ __nv_bfloat16 g_w2t_lo[(size_t)EE * HH * DD];

// ---------------- helpers ----------------
__device__ __forceinline__ uint32_t smem_u32(const void* p) {
    uint32_t a;
    asm("{ .reg .u64 t; cvta.to.shared.u64 t, %1; cvt.u32.u64 %0, t; }" : "=r"(a) : "l"(p));
    return a;
}
__device__ __forceinline__ void cp16(uint32_t s, const void* g) {
    asm volatile("cp.async.cg.shared.global [%0], [%1], 16;" :: "r"(s), "l"(g));
}
#define CP_COMMIT() asm volatile("cp.async.commit_group;" ::: "memory")
#define CP_WAIT(n)  asm volatile("cp.async.wait_group %0;" :: "n"(n) : "memory")

__device__ __forceinline__ void ldsm4(uint32_t* r, uint32_t a) {
    asm volatile("ldmatrix.sync.aligned.m8n8.x4.shared.b16 {%0,%1,%2,%3}, [%4];"
                 : "=r"(r[0]), "=r"(r[1]), "=r"(r[2]), "=r"(r[3]) : "r"(a));
}
__device__ __forceinline__ void mma16816(float* c, const uint32_t* a, uint32_t b0, uint32_t b1) {
    asm volatile("mma.sync.aligned.m16n8k16.row.col.f32.bf16.bf16.f32 "
                 "{%0,%1,%2,%3}, {%4,%5,%6,%7}, {%8,%9}, {%0,%1,%2,%3};"
                 : "+f"(c[0]), "+f"(c[1]), "+f"(c[2]), "+f"(c[3])
                 : "r"(a[0]), "r"(a[1]), "r"(a[2]), "r"(a[3]), "r"(b0), "r"(b1));
}
__device__ __forceinline__ uint32_t pack2(float a, float b) {
    __nv_bfloat16 h0 = __float2bfloat16(a), h1 = __float2bfloat16(b);
    return (uint32_t)__bfloat16_as_ushort(h0) | ((uint32_t)__bfloat16_as_ushort(h1) << 16);
}

// ---------------------------------------------------------------------------
// Kernel 0: zero output + reset counters
// ---------------------------------------------------------------------------
__global__ void zero_kernel(float4* __restrict__ out) {
    int i = blockIdx.x * blockDim.x + threadIdx.x;
    out[i] = make_float4(0.f, 0.f, 0.f, 0.f);
    if (blockIdx.x == 0 && threadIdx.x < EE) g_cnt[threadIdx.x] = 0;
}

// ---------------------------------------------------------------------------
// Kernel 1: router (fp32, validated)
// ---------------------------------------------------------------------------
__global__ __launch_bounds__(256) void router_kernel(const float* __restrict__ x,
                                                     const float* __restrict__ rw) {
    int n = blockIdx.x, tid = threadIdx.x;
    const float* xr = x + (size_t)n * DD;
    float acc[EE];
#pragma unroll
    for (int e = 0; e < EE; e++) acc[e] = 0.f;
    for (int i = tid; i < DD; i += 256) {
        float xv = xr[i];
#pragma unroll
        for (int e = 0; e < EE; e++) acc[e] += xv * rw[e * DD + i];
    }
#pragma unroll
    for (int e = 0; e < EE; e++)
#pragma unroll
        for (int o = 16; o > 0; o >>= 1) acc[e] += __shfl_down_sync(0xffffffffu, acc[e], o);

    __shared__ float sm[8][EE];
    int warp = tid >> 5, lane = tid & 31;
    if (lane == 0)
#pragma unroll
        for (int e = 0; e < EE; e++) sm[warp][e] = acc[e];
    __syncthreads();

    if (tid == 0) {
        float logits[EE];
#pragma unroll
        for (int e = 0; e < EE; e++) {
            float s = 0.f;
#pragma unroll
            for (int w = 0; w < 8; w++) s += sm[w][e];
            logits[e] = s;
        }
        int i0 = 0; float v0 = logits[0];
#pragma unroll
        for (int e = 1; e < EE; e++) if (logits[e] > v0) { v0 = logits[e]; i0 = e; }
        int i1 = 0; float v1 = -3.0e38f;
#pragma unroll
        for (int e = 0; e < EE; e++) if (e != i0 && logits[e] > v1) { v1 = logits[e]; i1 = e; }
        float ex = __expf(v1 - v0);
        float g0 = 1.f / (1.f + ex);
        float g1 = ex * g0;
        int p0 = atomicAdd(&g_cnt[i0], 1);
        g_tok[i0 * NN + p0] = n;  g_gate[i0 * NN + p0] = g0;
        int p1 = atomicAdd(&g_cnt[i1], 1);
        g_tok[i1 * NN + p1] = n;  g_gate[i1 * NN + p1] = g1;
    }
}

// ---------------------------------------------------------------------------
// Kernel 2: gather tokens per expert, split fp32 -> bf16 hi/lo, pad to 128
// ---------------------------------------------------------------------------
__global__ __launch_bounds__(256) void gather_kernel(const float* __restrict__ x) {
    int e = blockIdx.y, slot = blockIdx.x;
    int cnt = g_cnt[e];
    int pad = (cnt + 127) & ~127;  if (pad > NN) pad = NN;
    if (slot >= pad) return;
    size_t dst = ((size_t)e * NN + slot) * DD;
    int i = threadIdx.x;
    if (slot < cnt) {
        int tok = g_tok[e * NN + slot];
        float4 v = ((const float4*)(x + (size_t)tok * DD))[i];
        __nv_bfloat16 h0 = __float2bfloat16(v.x), h1 = __float2bfloat16(v.y);
        __nv_bfloat16 h2 = __float2bfloat16(v.z), h3 = __float2bfloat16(v.w);
        uint2 hw, lw;
        hw.x = (uint32_t)__bfloat16_as_ushort(h0) | ((uint32_t)__bfloat16_as_ushort(h1) << 16);
        hw.y = (uint32_t)__bfloat16_as_ushort(h2) | ((uint32_t)__bfloat16_as_ushort(h3) << 16);
        lw.x = pack2(v.x - __bfloat162float(h0), v.y - __bfloat162float(h1));
        lw.y = pack2(v.z - __bfloat162float(h2), v.w - __bfloat162float(h3));
        ((uint2*)(g_xg_hi + dst))[i] = hw;
        ((uint2*)(g_xg_lo + dst))[i] = lw;
    } else {
        ((uint2*)(g_xg_hi + dst))[i] = make_uint2(0, 0);
        ((uint2*)(g_xg_lo + dst))[i] = make_uint2(0, 0);
    }
}

// ---------------------------------------------------------------------------
// Kernels 3/4: transpose + split weights  [E][R][C] fp32 -> [E][C][R] bf16 hi/lo
// ---------------------------------------------------------------------------
template<int R, int C, int WHICH>
__global__ __launch_bounds__(256) void wsplit_kernel(const float* __restrict__ w) {
    __shared__ float t[32][33];
    int e = blockIdx.z;
    int c0 = blockIdx.x * 32, r0 = blockIdx.y * 32;
    const float* src = w + (size_t)e * R * C;
    int tx = threadIdx.x & 31, ty = threadIdx.x >> 5;
#pragma unroll
    for (int i = 0; i < 4; i++)
        t[ty + i * 8][tx] = src[(size_t)(r0 + ty + i * 8) * C + c0 + tx];
    __syncthreads();
    __nv_bfloat16* hi = (WHICH == 0) ? g_w1t_hi : g_w2t_hi;
    __nv_bfloat16* lo = (WHICH == 0) ? g_w1t_lo : g_w2t_lo;
#pragma unroll
    for (int i = 0; i < 4; i++) {
        float v = t[tx][ty + i * 8];
        size_t o = ((size_t)e * C + c0 + ty + i * 8) * R + r0 + tx;
        __nv_bfloat16 h = __float2bfloat16(v);
        hi[o] = h;
        lo[o] = __float2bfloat16(v - __bfloat162float(h));
    }
}

// ---------------------------------------------------------------------------
// mma.sync grouped GEMM.  D[128x256] += A[128xK] * B^T[256xK], bf16 hi/lo split.
// smem plane element (m,k): m*64 + ((k>>3) ^ ((m>>1)&3))*16 + (k&7)*2
// ---------------------------------------------------------------------------
template<int KTOT, bool IS_G1>
__global__ __launch_bounds__(256, 1) void gemm_mma(float* __restrict__ out) {
    constexpr int KC = KTOT / TK;
    int e   = blockIdx.z;
    int cnt = g_cnt[e];
    int m0  = blockIdx.y * TM;
    if (m0 >= cnt) return;
    int n0  = blockIdx.x * TN;

    extern __shared__ char smem[];
    uint32_t sb = smem_u32(smem);

    const __nv_bfloat16 *Ahi, *Alo, *Bhi, *Blo;
    if (IS_G1) {
        Ahi = g_xg_hi + ((size_t)e * NN + m0) * KTOT;
        Alo = g_xg_lo + ((size_t)e * NN + m0) * KTOT;
        Bhi = g_w1t_hi + ((size_t)e * HH + n0) * KTOT;
        Blo = g_w1t_lo + ((size_t)e * HH + n0) * KTOT;
    } else {
        Ahi = g_h_hi + ((size_t)e * NN + m0) * KTOT;
        Alo = g_h_lo + ((size_t)e * NN + m0) * KTOT;
        Bhi = g_w2t_hi + ((size_t)e * DD + n0) * KTOT;
        Blo = g_w2t_lo + ((size_t)e * DD + n0) * KTOT;
    }

    int tid = threadIdx.x;
    // ---- cp.async mapping ----
    // A planes (128 rows x 64B): row = tid>>1, two 16B chunks
    int arow_i = tid >> 1;
    int lc0    = (tid & 1) * 2;
    int aswl   = (arow_i >> 1) & 3;
    uint32_t adrow = (uint32_t)arow_i * 64;
    uint32_t ad0 = adrow + (uint32_t)((lc0 ^ aswl) << 4);
    uint32_t ad1 = adrow + (uint32_t)(((lc0 + 1) ^ aswl) << 4);
    size_t aro = (size_t)arow_i * KTOT;
    // B planes (256 rows x 64B): row = tid, all 4 16B chunks
    int bswl = (tid >> 1) & 3;
    uint32_t bdrow = (uint32_t)tid * 64;
    size_t bro = (size_t)tid * KTOT;

    auto issue = [&](int j) {
        uint32_t st = sb + (uint32_t)(j & (STAGES - 1)) * STAGE_BYTES;
        int kb = j * TK;
        cp16(st + ad0,        Ahi + aro + kb + lc0 * 8);
        cp16(st + ad1,        Ahi + aro + kb + lc0 * 8 + 8);
        cp16(st + A_LO + ad0, Alo + aro + kb + lc0 * 8);
        cp16(st + A_LO + ad1, Alo + aro + kb + lc0 * 8 + 8);
#pragma unroll
        for (int kq = 0; kq < 4; kq++) {
            uint32_t d = bdrow + (uint32_t)((kq ^ bswl) << 4);
            cp16(st + B_HI + d, Bhi + bro + kb + kq * 8);
            cp16(st + B_LO + d, Blo + bro + kb + kq * 8);
        }
    };

    issue(0); CP_COMMIT();
    issue(1); CP_COMMIT();
    issue(2); CP_COMMIT();

    // ---- warp / lane geometry: 2 warps M x 4 warps N, warp tile 64x64 ----
    int wid = tid >> 5, lane = tid & 31;
    int wm = wid & 1;          // rows wm*64
    int wn = wid >> 1;         // cols wn*64
    int li = lane >> 3;
    int lr = lane & 7;
    int kadd = li >> 1;
    int rsel = (li & 1) * 8 + lr;

    uint32_t abase[4]; int asw[4];
#pragma unroll
    for (int mt = 0; mt < 4; mt++) {
        int m = wm * 64 + mt * 16 + rsel;
        abase[mt] = (uint32_t)m * 64;
        asw[mt] = (m >> 1) & 3;
    }
    uint32_t bbase[4]; int bsw[4];
#pragma unroll
    for (int p = 0; p < 4; p++) {
        int n = wn * 64 + p * 16 + rsel;
        bbase[p] = (uint32_t)n * 64;
        bsw[p] = (n >> 1) & 3;
    }

    float acc[4][8][4];
#pragma unroll
    for (int a = 0; a < 4; a++)
#pragma unroll
        for (int b = 0; b < 8; b++)
#pragma unroll
            for (int c = 0; c < 4; c++) acc[a][b][c] = 0.f;

    for (int j = 0; j < KC; j++) {
        CP_WAIT(2);
        __syncthreads();
        if (j + 3 < KC) issue(j + 3);
        CP_COMMIT();
        uint32_t st = sb + (uint32_t)(j & (STAGES - 1)) * STAGE_BYTES;
#pragma unroll
        for (int kq = 0; kq < 4; kq += 2) {
            uint32_t ahi[4][4], alo[4][4];
#pragma unroll
            for (int mt = 0; mt < 4; mt++) {
                uint32_t off = abase[mt] + (uint32_t)((((kq + kadd) ^ asw[mt])) << 4);
                ldsm4(ahi[mt], st + off);
                ldsm4(alo[mt], st + A_LO + off);
            }
#pragma unroll
            for (int p = 0; p < 4; p++) {
                uint32_t bh[4], bl[4];
                uint32_t off = bbase[p] + (uint32_t)((((kq + kadd) ^ bsw[p])) << 4);
                ldsm4(bh, st + B_HI + off);
                ldsm4(bl, st + B_LO + off);
#pragma unroll
                for (int mt = 0; mt < 4; mt++) {
#pragma unroll
                    for (int s = 0; s < 2; s++) {
                        float* c = acc[mt][p * 2 + s];
                        mma16816(c, ahi[mt], bh[s], bh[2 + s]);
                        mma16816(c, ahi[mt], bl[s], bl[2 + s]);
                        mma16816(c, alo[mt], bh[s], bh[2 + s]);
                    }
                }
            }
        }
    }

    // ---- epilogue ----
    int r4 = lane >> 2, cpair = (lane & 3) * 2;
    if (IS_G1) {
#pragma unroll
        for (int mt = 0; mt < 4; mt++) {
            int gm = m0 + wm * 64 + mt * 16;
#pragma unroll
            for (int q = 0; q < 8; q++) {
                int gn = n0 + wn * 64 + q * 8 + cpair;
#pragma unroll
                for (int half = 0; half < 2; half++) {
                    int row = gm + r4 + half * 8;
                    float v0 = acc[mt][q][half * 2 + 0];
                    float v1 = acc[mt][q][half * 2 + 1];
                    v0 = fmaxf(v0, 0.f); v0 *= v0;
                    v1 = fmaxf(v1, 0.f); v1 *= v1;
                    __nv_bfloat16 h0 = __float2bfloat16(v0), h1 = __float2bfloat16(v1);
                    uint32_t hw = (uint32_t)__bfloat16_as_ushort(h0) |
                                  ((uint32_t)__bfloat16_as_ushort(h1) << 16);
                    uint32_t lw = pack2(v0 - __bfloat162float(h0), v1 - __bfloat162float(h1));
                    size_t o = ((size_t)e * NN + row) * HH + gn;
                    *(uint32_t*)(g_h_hi + o) = hw;
                    *(uint32_t*)(g_h_lo + o) = lw;
                }
            }
        }
    } else {
#pragma unroll
        for (int mt = 0; mt < 4; mt++) {
            int gm = m0 + wm * 64 + mt * 16;
            int   tokh[2];
            float gth[2];
#pragma unroll
            for (int half = 0; half < 2; half++) {
                int slot = gm + r4 + half * 8;
                bool ok = slot < cnt;
                tokh[half] = ok ? g_tok[e * NN + slot] : -1;
                gth[half]  = ok ? g_gate[e * NN + slot] : 0.f;
            }
#pragma unroll
            for (int q = 0; q < 8; q++) {
                int gn = n0 + wn * 64 + q * 8 + cpair;
#pragma unroll
                for (int half = 0; half < 2; half++) {
                    if (tokh[half] >= 0) {
                        float* orow = out + (size_t)tokh[half] * DD + gn;
                        atomicAdd(orow,     gth[half] * acc[mt][q][half * 2 + 0]);
                        atomicAdd(orow + 1, gth[half] * acc[mt][q][half * 2 + 1]);
                    }
                }
            }
        }
    }
}

// ---------------------------------------------------------------------------
extern "C" void kernel_launch(void* const* d_in, const int* in_sizes, int n_in,
                              void* d_out, int out_size) {
    const float* x  = (const float*)d_in[0];   // (B,T,D)
    const float* rw = (const float*)d_in[1];   // (E,D)
    const float* w1 = (const float*)d_in[2];   // (E,D,H)
    const float* w2 = (const float*)d_in[3];   // (E,H,D)
    float* out = (float*)d_out;                // (B,T,D) fp32

    cudaFuncSetAttribute(gemm_mma<DD, true>,  cudaFuncAttributeMaxDynamicSharedMemorySize, SMEM_BYTES);
    cudaFuncSetAttribute(gemm_mma<HH, false>, cudaFuncAttributeMaxDynamicSharedMemorySize, SMEM_BYTES);

    int zblocks = out_size / (4 * 256);
    zero_kernel<<<zblocks, 256>>>((float4*)out);
    router_kernel<<<NN, 256>>>(x, rw);
    wsplit_kernel<DD, HH, 0><<<dim3(HH / 32, DD / 32, EE), 256>>>(w1);
    wsplit_kernel<HH, DD, 1><<<dim3(DD / 32, HH / 32, EE), 256>>>(w2);
    gather_kernel<<<dim3(NN, EE), 256>>>(x);
    gemm_mma<DD, true><<<dim3(HH / TN, NN / TM, EE), 256, SMEM_BYTES>>>(nullptr);
    gemm_mma<HH, false><<<dim3(DD / TN, NN / TM, EE), 256, SMEM_BYTES>>>(out);
}

// round 6
// speedup vs baseline: 1.2484x; 1.2484x over previous
#include <cuda_runtime.h>
#include <cuda_bf16.h>
#include <cstdint>

// ---------------- problem constants ----------------
#define DD   1024
#define EE   8
#define HH   2048
#define NN   8192   // B*T tokens

// GEMM tile config: CTA 128x256, 16 warps, warp tile 32x64 (4M x 4N), K-chunk 32
#define TM   128
#define TN   256
#define TK   32
#define STAGES 4
#define A_LO 8192
#define B_HI 16384
#define B_LO 32768
#define STAGE_BYTES 49152            // Ahi8K + Alo8K + Bhi16K + Blo16K
#define SMEM_BYTES  (STAGES*STAGE_BYTES)   // 192 KB

// ---------------- static device scratch ----------------
__device__ int   g_cnt[EE];
__device__ int   g_tok[EE * NN];
__device__ float g_gate[EE * NN];
__device__ __nv_bfloat16 g_xg_hi[(size_t)EE * NN * DD];
__device__ __nv_bfloat16 g_xg_lo[(size_t)EE * NN * DD];
__device__ __nv_bfloat16 g_h_hi [(size_t)EE * NN * HH];
__device__ __nv_bfloat16 g_h_lo [(size_t)EE * NN * HH];
__device__ __nv_bfloat16 g_w1t_hi[(size_t)EE * DD * HH];
__device__ __nv_bfloat16 g_w1t_lo[(size_t)EE * DD * HH];
__device__ __nv_bfloat16 g_w2t_hi[(size_t)EE * HH * DD];
__device__ __nv_bfloat16 g_w2t_lo[(size_t)EE * HH * DD];

// ---------------- helpers ----------------
__device__ __forceinline__ uint32_t smem_u32(const void* p) {
    uint32_t a;
    asm("{ .reg .u64 t; cvta.to.shared.u64 t, %1; cvt.u32.u64 %0, t; }" : "=r"(a) : "l"(p));
    return a;
}
__device__ __forceinline__ void cp16(uint32_t s, const void* g) {
    asm volatile("cp.async.cg.shared.global [%0], [%1], 16;" :: "r"(s), "l"(g));
}
#define CP_COMMIT() asm volatile("cp.async.commit_group;" ::: "memory")
#define CP_WAIT(n)  asm volatile("cp.async.wait_group %0;" :: "n"(n) : "memory")

__device__ __forceinline__ void ldsm4(uint32_t* r, uint32_t a) {
    asm volatile("ldmatrix.sync.aligned.m8n8.x4.shared.b16 {%0,%1,%2,%3}, [%4];"
                 : "=r"(r[0]), "=r"(r[1]), "=r"(r[2]), "=r"(r[3]) : "r"(a));
}
__device__ __forceinline__ void mma16816(float* c, const uint32_t* a, uint32_t b0, uint32_t b1) {
    asm volatile("mma.sync.aligned.m16n8k16.row.col.f32.bf16.bf16.f32 "
                 "{%0,%1,%2,%3}, {%4,%5,%6,%7}, {%8,%9}, {%0,%1,%2,%3};"
                 : "+f"(c[0]), "+f"(c[1]), "+f"(c[2]), "+f"(c[3])
                 : "r"(a[0]), "r"(a[1]), "r"(a[2]), "r"(a[3]), "r"(b0), "r"(b1));
}
__device__ __forceinline__ uint32_t pack2(float a, float b) {
    __nv_bfloat16 h0 = __float2bfloat16(a), h1 = __float2bfloat16(b);
    return (uint32_t)__bfloat16_as_ushort(h0) | ((uint32_t)__bfloat16_as_ushort(h1) << 16);
}

// ---------------------------------------------------------------------------
// Kernel 0: zero output + reset counters
// ---------------------------------------------------------------------------
__global__ void zero_kernel(float4* __restrict__ out) {
    int i = blockIdx.x * blockDim.x + threadIdx.x;
    out[i] = make_float4(0.f, 0.f, 0.f, 0.f);
    if (blockIdx.x == 0 && threadIdx.x < EE) g_cnt[threadIdx.x] = 0;
}

// ---------------------------------------------------------------------------
// Kernel 1: router (fp32, validated)
// ---------------------------------------------------------------------------
__global__ __launch_bounds__(256) void router_kernel(const float* __restrict__ x,
                                                     const float* __restrict__ rw) {
    int n = blockIdx.x, tid = threadIdx.x;
    const float* xr = x + (size_t)n * DD;
    float acc[EE];
#pragma unroll
    for (int e = 0; e < EE; e++) acc[e] = 0.f;
    for (int i = tid; i < DD; i += 256) {
        float xv = xr[i];
#pragma unroll
        for (int e = 0; e < EE; e++) acc[e] += xv * rw[e * DD + i];
    }
#pragma unroll
    for (int e = 0; e < EE; e++)
#pragma unroll
        for (int o = 16; o > 0; o >>= 1) acc[e] += __shfl_down_sync(0xffffffffu, acc[e], o);

    __shared__ float sm[8][EE];
    int warp = tid >> 5, lane = tid & 31;
    if (lane == 0)
#pragma unroll
        for (int e = 0; e < EE; e++) sm[warp][e] = acc[e];
    __syncthreads();

    if (tid == 0) {
        float logits[EE];
#pragma unroll
        for (int e = 0; e < EE; e++) {
            float s = 0.f;
#pragma unroll
            for (int w = 0; w < 8; w++) s += sm[w][e];
            logits[e] = s;
        }
        int i0 = 0; float v0 = logits[0];
#pragma unroll
        for (int e = 1; e < EE; e++) if (logits[e] > v0) { v0 = logits[e]; i0 = e; }
        int i1 = 0; float v1 = -3.0e38f;
#pragma unroll
        for (int e = 0; e < EE; e++) if (e != i0 && logits[e] > v1) { v1 = logits[e]; i1 = e; }
        float ex = __expf(v1 - v0);
        float g0 = 1.f / (1.f + ex);
        float g1 = ex * g0;
        int p0 = atomicAdd(&g_cnt[i0], 1);
        g_tok[i0 * NN + p0] = n;  g_gate[i0 * NN + p0] = g0;
        int p1 = atomicAdd(&g_cnt[i1], 1);
        g_tok[i1 * NN + p1] = n;  g_gate[i1 * NN + p1] = g1;
    }
}

// ---------------------------------------------------------------------------
// Kernel 2: gather tokens per expert, split fp32 -> bf16 hi/lo, pad to 128
// ---------------------------------------------------------------------------
__global__ __launch_bounds__(256) void gather_kernel(const float* __restrict__ x) {
    int e = blockIdx.y, slot = blockIdx.x;
    int cnt = g_cnt[e];
    int pad = (cnt + 127) & ~127;  if (pad > NN) pad = NN;
    if (slot >= pad) return;
    size_t dst = ((size_t)e * NN + slot) * DD;
    int i = threadIdx.x;
    if (slot < cnt) {
        int tok = g_tok[e * NN + slot];
        float4 v = ((const float4*)(x + (size_t)tok * DD))[i];
        __nv_bfloat16 h0 = __float2bfloat16(v.x), h1 = __float2bfloat16(v.y);
        __nv_bfloat16 h2 = __float2bfloat16(v.z), h3 = __float2bfloat16(v.w);
        uint2 hw, lw;
        hw.x = (uint32_t)__bfloat16_as_ushort(h0) | ((uint32_t)__bfloat16_as_ushort(h1) << 16);
        hw.y = (uint32_t)__bfloat16_as_ushort(h2) | ((uint32_t)__bfloat16_as_ushort(h3) << 16);
        lw.x = pack2(v.x - __bfloat162float(h0), v.y - __bfloat162float(h1));
        lw.y = pack2(v.z - __bfloat162float(h2), v.w - __bfloat162float(h3));
        ((uint2*)(g_xg_hi + dst))[i] = hw;
        ((uint2*)(g_xg_lo + dst))[i] = lw;
    } else {
        ((uint2*)(g_xg_hi + dst))[i] = make_uint2(0, 0);
        ((uint2*)(g_xg_lo + dst))[i] = make_uint2(0, 0);
    }
}

// ---------------------------------------------------------------------------
// Kernels 3/4: transpose + split weights  [E][R][C] fp32 -> [E][C][R] bf16 hi/lo
// ---------------------------------------------------------------------------
template<int R, int C, int WHICH>
__global__ __launch_bounds__(256) void wsplit_kernel(const float* __restrict__ w) {
    __shared__ float t[32][33];
    int e = blockIdx.z;
    int c0 = blockIdx.x * 32, r0 = blockIdx.y * 32;
    const float* src = w + (size_t)e * R * C;
    int tx = threadIdx.x & 31, ty = threadIdx.x >> 5;
#pragma unroll
    for (int i = 0; i < 4; i++)
        t[ty + i * 8][tx] = src[(size_t)(r0 + ty + i * 8) * C + c0 + tx];
    __syncthreads();
    __nv_bfloat16* hi = (WHICH == 0) ? g_w1t_hi : g_w2t_hi;
    __nv_bfloat16* lo = (WHICH == 0) ? g_w1t_lo : g_w2t_lo;
#pragma unroll
    for (int i = 0; i < 4; i++) {
        float v = t[tx][ty + i * 8];
        size_t o = ((size_t)e * C + c0 + ty + i * 8) * R + r0 + tx;
        __nv_bfloat16 h = __float2bfloat16(v);
        hi[o] = h;
        lo[o] = __float2bfloat16(v - __bfloat162float(h));
    }
}

// ---------------------------------------------------------------------------
// mma.sync grouped GEMM.  D[128x256] += A[128xKs] * B^T[256xKs], bf16 hi/lo split.
// 512 threads = 16 warps (4M x 4N), warp tile 32x64.
// KSLICES: split-K factor; z-block = e + EE*slice (G2 only; G2 epilogue is atomic).
// smem plane element (m,k): m*64 + ((k>>3) ^ ((m>>1)&3))*16 + (k&7)*2
// ---------------------------------------------------------------------------
template<int KTOT, int KSLICES, bool IS_G1>
__global__ __launch_bounds__(512, 1) void gemm_mma(float* __restrict__ out) {
    constexpr int KLEN = KTOT / KSLICES;
    constexpr int KC = KLEN / TK;
    int zz = blockIdx.z;
    int e = zz & (EE - 1);
    int slice = zz >> 3;
    int koff = slice * KLEN;
    int cnt = g_cnt[e];
    int m0  = blockIdx.y * TM;
    if (m0 >= cnt) return;
    int n0  = blockIdx.x * TN;

    extern __shared__ char smem[];
    uint32_t sb = smem_u32(smem);

    const __nv_bfloat16 *Ahi, *Alo, *Bhi, *Blo;
    if (IS_G1) {
        Ahi = g_xg_hi + ((size_t)e * NN + m0) * KTOT;
        Alo = g_xg_lo + ((size_t)e * NN + m0) * KTOT;
        Bhi = g_w1t_hi + ((size_t)e * HH + n0) * KTOT;
        Blo = g_w1t_lo + ((size_t)e * HH + n0) * KTOT;
    } else {
        Ahi = g_h_hi + ((size_t)e * NN + m0) * KTOT;
        Alo = g_h_lo + ((size_t)e * NN + m0) * KTOT;
        Bhi = g_w2t_hi + ((size_t)e * DD + n0) * KTOT;
        Blo = g_w2t_lo + ((size_t)e * DD + n0) * KTOT;
    }

    int tid = threadIdx.x;
    // ---- cp.async mapping (512 threads) ----
    // A planes: 128 rows x 4 16B-units -> 1 unit/thread
    int arow_i = tid >> 2;
    int au     = tid & 3;
    int aswl   = (arow_i >> 1) & 3;
    uint32_t adst = (uint32_t)arow_i * 64 + (uint32_t)((au ^ aswl) << 4);
    size_t aro = (size_t)arow_i * KTOT;
    // B planes: 256 rows x 4 units -> 2 units/thread
    int brow_i = tid >> 1;
    int bu0    = (tid & 1) * 2;
    int bswl   = (brow_i >> 1) & 3;
    uint32_t bdrow = (uint32_t)brow_i * 64;
    uint32_t bd0 = bdrow + (uint32_t)((bu0 ^ bswl) << 4);
    uint32_t bd1 = bdrow + (uint32_t)(((bu0 + 1) ^ bswl) << 4);
    size_t bro = (size_t)brow_i * KTOT;

    auto issue = [&](int j) {
        uint32_t st = sb + (uint32_t)(j & (STAGES - 1)) * STAGE_BYTES;
        int kb = koff + j * TK;
        cp16(st + adst,        Ahi + aro + kb + au * 8);
        cp16(st + A_LO + adst, Alo + aro + kb + au * 8);
        cp16(st + B_HI + bd0,  Bhi + bro + kb + bu0 * 8);
        cp16(st + B_HI + bd1,  Bhi + bro + kb + bu0 * 8 + 8);
        cp16(st + B_LO + bd0,  Blo + bro + kb + bu0 * 8);
        cp16(st + B_LO + bd1,  Blo + bro + kb + bu0 * 8 + 8);
    };

    issue(0); CP_COMMIT();
    issue(1); CP_COMMIT();
    issue(2); CP_COMMIT();

    // ---- warp / lane geometry: 4 warps M x 4 warps N, warp tile 32x64 ----
    int wid = tid >> 5, lane = tid & 31;
    int wm = wid & 3;          // rows wm*32
    int wn = wid >> 2;         // cols wn*64
    int li = lane >> 3;
    int lr = lane & 7;
    int kadd = li >> 1;
    int rsel = (li & 1) * 8 + lr;

    uint32_t abase[2]; int asw[2];
#pragma unroll
    for (int mt = 0; mt < 2; mt++) {
        int m = wm * 32 + mt * 16 + rsel;
        abase[mt] = (uint32_t)m * 64;
        asw[mt] = (m >> 1) & 3;
    }
    uint32_t bbase[4]; int bsw[4];
#pragma unroll
    for (int p = 0; p < 4; p++) {
        int n = wn * 64 + p * 16 + rsel;
        bbase[p] = (uint32_t)n * 64;
        bsw[p] = (n >> 1) & 3;
    }

    float acc[2][8][4];
#pragma unroll
    for (int a = 0; a < 2; a++)
#pragma unroll
        for (int b = 0; b < 8; b++)
#pragma unroll
            for (int c = 0; c < 4; c++) acc[a][b][c] = 0.f;

    for (int j = 0; j < KC; j++) {
        CP_WAIT(2);
        __syncthreads();
        if (j + 3 < KC) issue(j + 3);
        CP_COMMIT();
        uint32_t st = sb + (uint32_t)(j & (STAGES - 1)) * STAGE_BYTES;
#pragma unroll
        for (int kq = 0; kq < 4; kq += 2) {
            uint32_t ahi[2][4], alo[2][4];
#pragma unroll
            for (int mt = 0; mt < 2; mt++) {
                uint32_t off = abase[mt] + (uint32_t)((((kq + kadd) ^ asw[mt])) << 4);
                ldsm4(ahi[mt], st + off);
                ldsm4(alo[mt], st + A_LO + off);
            }
#pragma unroll
            for (int p = 0; p < 4; p++) {
                uint32_t bh[4], bl[4];
                uint32_t off = bbase[p] + (uint32_t)((((kq + kadd) ^ bsw[p])) << 4);
                ldsm4(bh, st + B_HI + off);
                ldsm4(bl, st + B_LO + off);
#pragma unroll
                for (int mt = 0; mt < 2; mt++) {
#pragma unroll
                    for (int s = 0; s < 2; s++) {
                        float* c = acc[mt][p * 2 + s];
                        mma16816(c, ahi[mt], bh[s], bh[2 + s]);
                        mma16816(c, ahi[mt], bl[s], bl[2 + s]);
                        mma16816(c, alo[mt], bh[s], bh[2 + s]);
                    }
                }
            }
        }
        __syncthreads();
    }

    // ---- epilogue ----
    int r4 = lane >> 2, cpair = (lane & 3) * 2;
    if (IS_G1) {
#pragma unroll
        for (int mt = 0; mt < 2; mt++) {
            int gm = m0 + wm * 32 + mt * 16;
#pragma unroll
            for (int q = 0; q < 8; q++) {
                int gn = n0 + wn * 64 + q * 8 + cpair;
#pragma unroll
                for (int half = 0; half < 2; half++) {
                    int row = gm + r4 + half * 8;
                    float v0 = acc[mt][q][half * 2 + 0];
                    float v1 = acc[mt][q][half * 2 + 1];
                    v0 = fmaxf(v0, 0.f); v0 *= v0;
                    v1 = fmaxf(v1, 0.f); v1 *= v1;
                    __nv_bfloat16 h0 = __float2bfloat16(v0), h1 = __float2bfloat16(v1);
                    uint32_t hw = (uint32_t)__bfloat16_as_ushort(h0) |
                                  ((uint32_t)__bfloat16_as_ushort(h1) << 16);
                    uint32_t lw = pack2(v0 - __bfloat162float(h0), v1 - __bfloat162float(h1));
                    size_t o = ((size_t)e * NN + row) * HH + gn;
                    *(uint32_t*)(g_h_hi + o) = hw;
                    *(uint32_t*)(g_h_lo + o) = lw;
                }
            }
        }
    } else {
#pragma unroll
        for (int mt = 0; mt < 2; mt++) {
            int gm = m0 + wm * 32 + mt * 16;
            int   tokh[2];
            float gth[2];
#pragma unroll
            for (int half = 0; half < 2; half++) {
                int slot = gm + r4 + half * 8;
                bool ok = slot < cnt;
                tokh[half] = ok ? g_tok[e * NN + slot] : -1;
                gth[half]  = ok ? g_gate[e * NN + slot] : 0.f;
            }
#pragma unroll
            for (int q = 0; q < 8; q++) {
                int gn = n0 + wn * 64 + q * 8 + cpair;
#pragma unroll
                for (int half = 0; half < 2; half++) {
                    if (tokh[half] >= 0) {
                        float* orow = out + (size_t)tokh[half] * DD + gn;
                        atomicAdd(orow,     gth[half] * acc[mt][q][half * 2 + 0]);
                        atomicAdd(orow + 1, gth[half] * acc[mt][q][half * 2 + 1]);
                    }
                }
            }
        }
    }
}

// ---------------------------------------------------------------------------
extern "C" void kernel_launch(void* const* d_in, const int* in_sizes, int n_in,
                              void* d_out, int out_size) {
    const float* x  = (const float*)d_in[0];   // (B,T,D)
    const float* rw = (const float*)d_in[1];   // (E,D)
    const float* w1 = (const float*)d_in[2];   // (E,D,H)
    const float* w2 = (const float*)d_in[3];   // (E,H,D)
    float* out = (float*)d_out;                // (B,T,D) fp32

    cudaFuncSetAttribute(gemm_mma<DD, 1, true>,  cudaFuncAttributeMaxDynamicSharedMemorySize, SMEM_BYTES);
    cudaFuncSetAttribute(gemm_mma<HH, 2, false>, cudaFuncAttributeMaxDynamicSharedMemorySize, SMEM_BYTES);

    int zblocks = out_size / (4 * 256);
    zero_kernel<<<zblocks, 256>>>((float4*)out);
    router_kernel<<<NN, 256>>>(x, rw);
    wsplit_kernel<DD, HH, 0><<<dim3(HH / 32, DD / 32, EE), 256>>>(w1);
    wsplit_kernel<HH, DD, 1><<<dim3(DD / 32, HH / 32, EE), 256>>>(w2);
    gather_kernel<<<dim3(NN, EE), 256>>>(x);
    gemm_mma<DD, 1, true><<<dim3(HH / TN, NN / TM, EE), 512, SMEM_BYTES>>>(nullptr);
    gemm_mma<HH, 2, false><<<dim3(DD / TN, NN / TM, EE * 2), 512, SMEM_BYTES>>>(out);
}

// round 7
// speedup vs baseline: 1.4389x; 1.1526x over previous
#include <cuda_runtime.h>
#include <cuda_bf16.h>
#include <cstdint>

// ---------------- problem constants ----------------
#define DD   1024
#define EE   8
#define HH   2048
#define NN   8192   // B*T tokens

// GEMM tile config: CTA 128x256, 16 warps (4M x 4N), warp tile 32x64, K-chunk 32
#define TM   128
#define TN   256
#define TK   32
#define A_LO 8192
#define B_HI 16384
#define B_LO 32768
#define STAGE_BYTES 49152            // Ahi8K + Alo8K + Bhi16K + Blo16K
#define SMEM_BYTES  (4*STAGE_BYTES + 64)   // 4 stages + mbarriers

// Tiled-plane geometry:
//  A planes: per (e, mblock, kchunk): 8192B, 128 rows x 64B, swizzled
//  B planes: per (e, nblock, kchunk): 16384B, 256 rows x 64B, swizzled
//  row byte: m*64 + ((u ^ ((m>>1)&3))<<4) + (k&7)*2,  u = (k>>3)&3

// ---------------- static device scratch ----------------
__device__ int   g_cnt[EE];
__device__ int   g_tok[EE * NN];
__device__ float g_gate[EE * NN];
__device__ __nv_bfloat16 g_xg_hi[(size_t)EE * NN * DD];   // [e][mb<64][kc<32][8KB]
__device__ __nv_bfloat16 g_xg_lo[(size_t)EE * NN * DD];
__device__ __nv_bfloat16 g_h_hi [(size_t)EE * NN * HH];   // [e][mb<64][kc<64][8KB]
__device__ __nv_bfloat16 g_h_lo [(size_t)EE * NN * HH];
__device__ __nv_bfloat16 g_w1t_hi[(size_t)EE * DD * HH];  // [e][nb<8][kc<32][16KB]
__device__ __nv_bfloat16 g_w1t_lo[(size_t)EE * DD * HH];
__device__ __nv_bfloat16 g_w2t_hi[(size_t)EE * HH * DD];  // [e][nb<4][kc<64][16KB]
__device__ __nv_bfloat16 g_w2t_lo[(size_t)EE * HH * DD];

// ---------------- helpers ----------------
__device__ __forceinline__ uint32_t smem_u32(const void* p) {
    uint32_t a;
    asm("{ .reg .u64 t; cvta.to.shared.u64 t, %1; cvt.u32.u64 %0, t; }" : "=r"(a) : "l"(p));
    return a;
}
__device__ __forceinline__ void ldsm4(uint32_t* r, uint32_t a) {
    asm volatile("ldmatrix.sync.aligned.m8n8.x4.shared.b16 {%0,%1,%2,%3}, [%4];"
                 : "=r"(r[0]), "=r"(r[1]), "=r"(r[2]), "=r"(r[3]) : "r"(a));
}
__device__ __forceinline__ void mma16816(float* c, const uint32_t* a, uint32_t b0, uint32_t b1) {
    asm volatile("mma.sync.aligned.m16n8k16.row.col.f32.bf16.bf16.f32 "
                 "{%0,%1,%2,%3}, {%4,%5,%6,%7}, {%8,%9}, {%0,%1,%2,%3};"
                 : "+f"(c[0]), "+f"(c[1]), "+f"(c[2]), "+f"(c[3])
                 : "r"(a[0]), "r"(a[1]), "r"(a[2]), "r"(a[3]), "r"(b0), "r"(b1));
}
__device__ __forceinline__ uint32_t pack2(float a, float b) {
    __nv_bfloat16 h0 = __float2bfloat16(a), h1 = __float2bfloat16(b);
    return (uint32_t)__bfloat16_as_ushort(h0) | ((uint32_t)__bfloat16_as_ushort(h1) << 16);
}
#define MBAR_INIT(a, c) asm volatile("mbarrier.init.shared.b64 [%0], %1;" :: "r"(a), "r"((uint32_t)(c)) : "memory")
#define MBAR_EXPECT_TX(a, tx) asm volatile("mbarrier.arrive.expect_tx.shared.b64 _, [%0], %1;" :: "r"(a), "r"((uint32_t)(tx)) : "memory")
#define MBAR_WAIT(a, ph) do { \
    uint32_t _m = (a); uint32_t _p = (uint32_t)(ph); uint32_t _d; \
    asm volatile("{\n\t.reg .pred p;\n\tmbarrier.try_wait.parity.acquire.cta.shared::cta.b64 p, [%1], %2;\n\tselp.b32 %0,1,0,p;\n\t}" \
        : "=r"(_d) : "r"(_m), "r"(_p) : "memory"); \
    if (!_d) { \
        asm volatile("{\n\t.reg .pred P1;\n\tWL_%=:\n\tmbarrier.try_wait.parity.acquire.cta.shared::cta.b64 P1, [%0], %1, 0x989680;\n\t@P1 bra.uni WD_%=;\n\tbra.uni WL_%=;\n\tWD_%=:\n\t}" \
            :: "r"(_m), "r"(_p) : "memory"); \
    } } while (0)
__device__ __forceinline__ void bulk_g2s(uint32_t dst, const void* src, uint32_t bytes, uint32_t mbar) {
    asm volatile("cp.async.bulk.shared::cta.global.mbarrier::complete_tx::bytes [%0], [%1], %2, [%3];"
                 :: "r"(dst), "l"(src), "r"(bytes), "r"(mbar) : "memory");
}

// pack 8 floats -> 16B hi plane + 16B lo plane
__device__ __forceinline__ void split8(const float* v, uint4& hi, uint4& lo) {
    uint32_t h[4], l[4];
#pragma unroll
    for (int i = 0; i < 4; i++) {
        __nv_bfloat16 a = __float2bfloat16(v[2*i]), b = __float2bfloat16(v[2*i+1]);
        h[i] = (uint32_t)__bfloat16_as_ushort(a) | ((uint32_t)__bfloat16_as_ushort(b) << 16);
        l[i] = pack2(v[2*i] - __bfloat162float(a), v[2*i+1] - __bfloat162float(b));
    }
    hi = make_uint4(h[0], h[1], h[2], h[3]);
    lo = make_uint4(l[0], l[1], l[2], l[3]);
}

// ---------------------------------------------------------------------------
// Kernel 0: zero output + reset counters
// ---------------------------------------------------------------------------
__global__ void zero_kernel(float4* __restrict__ out) {
    int i = blockIdx.x * blockDim.x + threadIdx.x;
    out[i] = make_float4(0.f, 0.f, 0.f, 0.f);
    if (blockIdx.x == 0 && threadIdx.x < EE) g_cnt[threadIdx.x] = 0;
}

// ---------------------------------------------------------------------------
// Kernel 1: router (fp32, validated)
// ---------------------------------------------------------------------------
__global__ __launch_bounds__(256) void router_kernel(const float* __restrict__ x,
                                                     const float* __restrict__ rw) {
    int n = blockIdx.x, tid = threadIdx.x;
    const float* xr = x + (size_t)n * DD;
    float acc[EE];
#pragma unroll
    for (int e = 0; e < EE; e++) acc[e] = 0.f;
    for (int i = tid; i < DD; i += 256) {
        float xv = xr[i];
#pragma unroll
        for (int e = 0; e < EE; e++) acc[e] += xv * rw[e * DD + i];
    }
#pragma unroll
    for (int e = 0; e < EE; e++)
#pragma unroll
        for (int o = 16; o > 0; o >>= 1) acc[e] += __shfl_down_sync(0xffffffffu, acc[e], o);

    __shared__ float sm[8][EE];
    int warp = tid >> 5, lane = tid & 31;
    if (lane == 0)
#pragma unroll
        for (int e = 0; e < EE; e++) sm[warp][e] = acc[e];
    __syncthreads();

    if (tid == 0) {
        float logits[EE];
#pragma unroll
        for (int e = 0; e < EE; e++) {
            float s = 0.f;
#pragma unroll
            for (int w = 0; w < 8; w++) s += sm[w][e];
            logits[e] = s;
        }
        int i0 = 0; float v0 = logits[0];
#pragma unroll
        for (int e = 1; e < EE; e++) if (logits[e] > v0) { v0 = logits[e]; i0 = e; }
        int i1 = 0; float v1 = -3.0e38f;
#pragma unroll
        for (int e = 0; e < EE; e++) if (e != i0 && logits[e] > v1) { v1 = logits[e]; i1 = e; }
        float ex = __expf(v1 - v0);
        float g0 = 1.f / (1.f + ex);
        float g1 = ex * g0;
        int p0 = atomicAdd(&g_cnt[i0], 1);
        g_tok[i0 * NN + p0] = n;  g_gate[i0 * NN + p0] = g0;
        int p1 = atomicAdd(&g_cnt[i1], 1);
        g_tok[i1 * NN + p1] = n;  g_gate[i1 * NN + p1] = g1;
    }
}

// ---------------------------------------------------------------------------
// Kernel 2: gather tokens, split hi/lo into swizzled tiled A planes
// grid (NN, EE), 128 threads: thread t -> kc = t>>2, u = t&3 (16B per plane)
// ---------------------------------------------------------------------------
__global__ __launch_bounds__(128) void gather_kernel(const float* __restrict__ x) {
    int e = blockIdx.y, slot = blockIdx.x;
    int cnt = g_cnt[e];
    int pad = (cnt + 127) & ~127;  if (pad > NN) pad = NN;
    if (slot >= pad) return;
    int mb = slot >> 7, m = slot & 127;
    int t = threadIdx.x;
    int kc = t >> 2, u = t & 3;
    size_t plane = (((size_t)e * 64 + mb) * 32 + kc) * 8192;
    uint32_t off = (uint32_t)m * 64 + (uint32_t)((u ^ ((m >> 1) & 3)) << 4);
    uint8_t* dh = (uint8_t*)g_xg_hi + plane + off;
    uint8_t* dl = (uint8_t*)g_xg_lo + plane + off;
    if (slot < cnt) {
        int tok = g_tok[e * NN + slot];
        const float4* xs = (const float4*)(x + (size_t)tok * DD + t * 8);
        float v[8];
        float4 a = xs[0], b = xs[1];
        v[0]=a.x; v[1]=a.y; v[2]=a.z; v[3]=a.w; v[4]=b.x; v[5]=b.y; v[6]=b.z; v[7]=b.w;
        uint4 hi, lo;
        split8(v, hi, lo);
        *(uint4*)dh = hi;
        *(uint4*)dl = lo;
    } else {
        uint4 z = make_uint4(0,0,0,0);
        *(uint4*)dh = z;
        *(uint4*)dl = z;
    }
}

// ---------------------------------------------------------------------------
// Kernels 3/4: weights -> transposed, split, swizzled tiled B planes
// w [E][R][C] fp32 -> planes [E][nb=C/256][kc=R/32][16KB]
// grid (R/32, C/256, E), 256 threads: thread t = local n row
// ---------------------------------------------------------------------------
template<int R, int C, int WHICH>   // WHICH 0 -> w1t planes, 1 -> w2t planes
__global__ __launch_bounds__(256) void wsplit_kernel(const float* __restrict__ w) {
    int kc = blockIdx.x, nb = blockIdx.y, e = blockIdx.z;
    const float* src = w + (size_t)e * R * C;
    int t = threadIdx.x;
    int n = nb * 256 + t;
    float vals[32];
#pragma unroll
    for (int j = 0; j < 32; j++)
        vals[j] = src[(size_t)(kc * 32 + j) * C + n];
    __nv_bfloat16* hi = (WHICH == 0) ? g_w1t_hi : g_w2t_hi;
    __nv_bfloat16* lo = (WHICH == 0) ? g_w1t_lo : g_w2t_lo;
    size_t plane = (((size_t)e * (C / 256) + nb) * (R / 32) + kc) * 16384;
    int sw = (t >> 1) & 3;
    uint32_t rbase = (uint32_t)t * 64;
#pragma unroll
    for (int u = 0; u < 4; u++) {
        uint4 h4, l4;
        split8(vals + u * 8, h4, l4);
        uint32_t off = rbase + (uint32_t)((u ^ sw) << 4);
        *(uint4*)((uint8_t*)hi + plane + off) = h4;
        *(uint4*)((uint8_t*)lo + plane + off) = l4;
    }
}

// ---------------------------------------------------------------------------
// bulk-fed mma.sync grouped GEMM.  D[128x256] += A * B^T, bf16 hi/lo 3-pass.
// 512 threads (16 warps, 4Mx4N), 4-stage mbarrier pipeline, 4 bulk copies/chunk.
// ---------------------------------------------------------------------------
template<int KTOT, int KSLICES, bool IS_G1>
__global__ __launch_bounds__(512, 1) void gemm_mma(float* __restrict__ out) {
    constexpr int KCA = KTOT / 32;               // total k-chunks in plane arrays
    constexpr int KC  = (KTOT / KSLICES) / TK;   // chunks this CTA processes
    constexpr int NB  = (IS_G1 ? HH : DD) / TN;
    int zz = blockIdx.z;
    int e = zz & (EE - 1);
    int slice = zz >> 3;
    int kc0 = slice * KC;
    int cnt = g_cnt[e];
    int m0  = blockIdx.y * TM;
    if (m0 >= cnt) return;
    int mb  = blockIdx.y;
    int nb  = blockIdx.x;
    int n0  = nb * TN;

    extern __shared__ char smem[];
    uint32_t sb = smem_u32(smem);
    uint32_t mbase = sb + 4 * STAGE_BYTES;

    // gmem plane bases (bytes)
    const uint8_t *pAh, *pAl, *pBh, *pBl;
    if (IS_G1) {
        size_t ap = (((size_t)e * 64 + mb) * KCA) * 8192;
        size_t bp = (((size_t)e * NB + nb) * KCA) * 16384;
        pAh = (const uint8_t*)g_xg_hi + ap;  pAl = (const uint8_t*)g_xg_lo + ap;
        pBh = (const uint8_t*)g_w1t_hi + bp; pBl = (const uint8_t*)g_w1t_lo + bp;
    } else {
        size_t ap = (((size_t)e * 64 + mb) * KCA) * 8192;
        size_t bp = (((size_t)e * NB + nb) * KCA) * 16384;
        pAh = (const uint8_t*)g_h_hi + ap;   pAl = (const uint8_t*)g_h_lo + ap;
        pBh = (const uint8_t*)g_w2t_hi + bp; pBl = (const uint8_t*)g_w2t_lo + bp;
    }

    int tid = threadIdx.x;
    if (tid == 0) {
#pragma unroll
        for (int s = 0; s < 4; s++) MBAR_INIT(mbase + s * 8, 1);
    }
    __syncthreads();

    auto issue = [&](int j) {
        int s = j & 3;
        uint32_t st = sb + (uint32_t)s * STAGE_BYTES;
        uint32_t mb_s = mbase + s * 8;
        size_t kc = (size_t)(kc0 + j);
        MBAR_EXPECT_TX(mb_s, STAGE_BYTES);
        bulk_g2s(st,        pAh + kc * 8192, 8192, mb_s);
        bulk_g2s(st + A_LO, pAl + kc * 8192, 8192, mb_s);
        bulk_g2s(st + B_HI, pBh + kc * 16384, 16384, mb_s);
        bulk_g2s(st + B_LO, pBl + kc * 16384, 16384, mb_s);
    };
    if (tid == 0) {
#pragma unroll
        for (int j0 = 0; j0 < 4; j0++) if (j0 < KC) issue(j0);
    }

    // ---- warp / lane geometry: 4 warps M x 4 warps N, warp tile 32x64 ----
    int wid = tid >> 5, lane = tid & 31;
    int wm = wid & 3;
    int wn = wid >> 2;
    int li = lane >> 3;
    int lr = lane & 7;
    int kadd = li >> 1;
    int rsel = (li & 1) * 8 + lr;

    uint32_t abase[2]; int asw[2];
#pragma unroll
    for (int mt = 0; mt < 2; mt++) {
        int m = wm * 32 + mt * 16 + rsel;
        abase[mt] = (uint32_t)m * 64;
        asw[mt] = (m >> 1) & 3;
    }
    uint32_t bbase[4]; int bsw[4];
#pragma unroll
    for (int p = 0; p < 4; p++) {
        int n = wn * 64 + p * 16 + rsel;
        bbase[p] = (uint32_t)n * 64;
        bsw[p] = (n >> 1) & 3;
    }

    float acc[2][8][4];
#pragma unroll
    for (int a = 0; a < 2; a++)
#pragma unroll
        for (int b = 0; b < 8; b++)
#pragma unroll
            for (int c = 0; c < 4; c++) acc[a][b][c] = 0.f;

    for (int j = 0; j < KC; j++) {
        int s = j & 3;
        MBAR_WAIT(mbase + s * 8, (j >> 2) & 1);
        uint32_t st = sb + (uint32_t)s * STAGE_BYTES;
#pragma unroll
        for (int kq = 0; kq < 4; kq += 2) {
            uint32_t ahi[2][4], alo[2][4];
#pragma unroll
            for (int mt = 0; mt < 2; mt++) {
                uint32_t off = abase[mt] + (uint32_t)((((kq + kadd) ^ asw[mt])) << 4);
                ldsm4(ahi[mt], st + off);
                ldsm4(alo[mt], st + A_LO + off);
            }
#pragma unroll
            for (int p = 0; p < 4; p++) {
                uint32_t bh[4], bl[4];
                uint32_t off = bbase[p] + (uint32_t)((((kq + kadd) ^ bsw[p])) << 4);
                ldsm4(bh, st + B_HI + off);
                ldsm4(bl, st + B_LO + off);
#pragma unroll
                for (int mt = 0; mt < 2; mt++) {
#pragma unroll
                    for (int sgl = 0; sgl < 2; sgl++) {
                        float* c = acc[mt][p * 2 + sgl];
                        mma16816(c, ahi[mt], bh[sgl], bh[2 + sgl]);
                        mma16816(c, ahi[mt], bl[sgl], bl[2 + sgl]);
                        mma16816(c, alo[mt], bh[sgl], bh[2 + sgl]);
                    }
                }
            }
        }
        __syncthreads();                 // all reads of stage s done
        if (tid == 0 && j + 4 < KC) issue(j + 4);
    }

    // ---- epilogue ----
    int r4 = lane >> 2, cpair = (lane & 3) * 2;
    if (IS_G1) {
        // write h planes (swizzled tiled layout for G2 bulk loads)
        size_t planeH0 = (((size_t)e * 64 + mb) * 64) * 8192;
#pragma unroll
        for (int mt = 0; mt < 2; mt++) {
#pragma unroll
            for (int q = 0; q < 8; q++) {
                int kcH = (n0 >> 5) + wn * 2 + (q >> 2);
                int u = q & 3;
#pragma unroll
                for (int half = 0; half < 2; half++) {
                    int lm = wm * 32 + mt * 16 + r4 + half * 8;
                    float v0 = acc[mt][q][half * 2 + 0];
                    float v1 = acc[mt][q][half * 2 + 1];
                    v0 = fmaxf(v0, 0.f); v0 *= v0;
                    v1 = fmaxf(v1, 0.f); v1 *= v1;
                    __nv_bfloat16 h0 = __float2bfloat16(v0), h1 = __float2bfloat16(v1);
                    uint32_t hw = (uint32_t)__bfloat16_as_ushort(h0) |
                                  ((uint32_t)__bfloat16_as_ushort(h1) << 16);
                    uint32_t lw = pack2(v0 - __bfloat162float(h0), v1 - __bfloat162float(h1));
                    size_t off = planeH0 + (size_t)kcH * 8192 +
                                 (uint32_t)(lm * 64 + ((u ^ ((lm >> 1) & 3)) << 4) + cpair * 2);
                    *(uint32_t*)((uint8_t*)g_h_hi + off) = hw;
                    *(uint32_t*)((uint8_t*)g_h_lo + off) = lw;
                }
            }
        }
    } else {
#pragma unroll
        for (int mt = 0; mt < 2; mt++) {
            int gm = m0 + wm * 32 + mt * 16;
            int   tokh[2];
            float gth[2];
#pragma unroll
            for (int half = 0; half < 2; half++) {
                int slot = gm + r4 + half * 8;
                bool ok = slot < cnt;
                tokh[half] = ok ? g_tok[e * NN + slot] : -1;
                gth[half]  = ok ? g_gate[e * NN + slot] : 0.f;
            }
#pragma unroll
            for (int q = 0; q < 8; q++) {
                int gn = n0 + wn * 64 + q * 8 + cpair;
#pragma unroll
                for (int half = 0; half < 2; half++) {
                    if (tokh[half] >= 0) {
                        float* orow = out + (size_t)tokh[half] * DD + gn;
                        atomicAdd(orow,     gth[half] * acc[mt][q][half * 2 + 0]);
                        atomicAdd(orow + 1, gth[half] * acc[mt][q][half * 2 + 1]);
                    }
                }
            }
        }
    }
}

// ---------------------------------------------------------------------------
extern "C" void kernel_launch(void* const* d_in, const int* in_sizes, int n_in,
                              void* d_out, int out_size) {
    const float* x  = (const float*)d_in[0];   // (B,T,D)
    const float* rw = (const float*)d_in[1];   // (E,D)
    const float* w1 = (const float*)d_in[2];   // (E,D,H)
    const float* w2 = (const float*)d_in[3];   // (E,H,D)
    float* out = (float*)d_out;                // (B,T,D) fp32

    cudaFuncSetAttribute(gemm_mma<DD, 1, true>,  cudaFuncAttributeMaxDynamicSharedMemorySize, SMEM_BYTES);
    cudaFuncSetAttribute(gemm_mma<HH, 2, false>, cudaFuncAttributeMaxDynamicSharedMemorySize, SMEM_BYTES);

    int zblocks = out_size / (4 * 256);
    zero_kernel<<<zblocks, 256>>>((float4*)out);
    router_kernel<<<NN, 256>>>(x, rw);
    wsplit_kernel<DD, HH, 0><<<dim3(DD / 32, HH / 256, EE), 256>>>(w1);
    wsplit_kernel<HH, DD, 1><<<dim3(HH / 32, DD / 256, EE), 256>>>(w2);
    gather_kernel<<<dim3(NN, EE), 128>>>(x);
    gemm_mma<DD, 1, true><<<dim3(HH / TN, NN / TM, EE), 512, SMEM_BYTES>>>(nullptr);
    gemm_mma<HH, 2, false><<<dim3(DD / TN, NN / TM, EE * 2), 512, SMEM_BYTES>>>(out);
}

// round 8
// speedup vs baseline: 1.5218x; 1.0576x over previous
#include <cuda_runtime.h>
#include <cuda_bf16.h>
#include <cstdint>

// ---------------- problem constants ----------------
#define DD   1024
#define EE   8
#define HH   2048
#define NN   8192   // B*T tokens

// GEMM tile config: CTA 128x256, 16 warps (4M x 4N), warp tile 32x64, K-chunk 32
#define TM   128
#define TN   256
#define TK   32
#define A_LO 8192
#define B_HI 16384
#define B_LO 32768
#define STAGE_BYTES 49152            // Ahi8K + Alo8K + Bhi16K + Blo16K
#define SMEM_BYTES  (4*STAGE_BYTES + 64)   // 4 stages + full/empty mbarriers

// Tiled-plane geometry:
//  A planes: per (e, mblock, kchunk): 8192B, 128 rows x 64B, swizzled
//  B planes: per (e, nblock, kchunk): 16384B, 256 rows x 64B, swizzled
//  row byte: m*64 + ((u ^ ((m>>1)&3))<<4) + (k&7)*2,  u = (k>>3)&3

// ---------------- static device scratch ----------------
__device__ int   g_cnt[EE];
__device__ int   g_tok[EE * NN];
__device__ float g_gate[EE * NN];
__device__ __nv_bfloat16 g_xg_hi[(size_t)EE * NN * DD];   // [e][mb<64][kc<32][8KB]
__device__ __nv_bfloat16 g_xg_lo[(size_t)EE * NN * DD];
__device__ __nv_bfloat16 g_h_hi [(size_t)EE * NN * HH];   // [e][mb<64][kc<64][8KB]
__device__ __nv_bfloat16 g_h_lo [(size_t)EE * NN * HH];
__device__ __nv_bfloat16 g_w1t_hi[(size_t)EE * DD * HH];  // [e][nb<8][kc<32][16KB]
__device__ __nv_bfloat16 g_w1t_lo[(size_t)EE * DD * HH];
__device__ __nv_bfloat16 g_w2t_hi[(size_t)EE * HH * DD];  // [e][nb<4][kc<64][16KB]
__device__ __nv_bfloat16 g_w2t_lo[(size_t)EE * HH * DD];

// ---------------- helpers ----------------
__device__ __forceinline__ uint32_t smem_u32(const void* p) {
    uint32_t a;
    asm("{ .reg .u64 t; cvta.to.shared.u64 t, %1; cvt.u32.u64 %0, t; }" : "=r"(a) : "l"(p));
    return a;
}
__device__ __forceinline__ void ldsm4(uint32_t* r, uint32_t a) {
    asm volatile("ldmatrix.sync.aligned.m8n8.x4.shared.b16 {%0,%1,%2,%3}, [%4];"
                 : "=r"(r[0]), "=r"(r[1]), "=r"(r[2]), "=r"(r[3]) : "r"(a));
}
__device__ __forceinline__ void mma16816(float* c, const uint32_t* a, uint32_t b0, uint32_t b1) {
    asm volatile("mma.sync.aligned.m16n8k16.row.col.f32.bf16.bf16.f32 "
                 "{%0,%1,%2,%3}, {%4,%5,%6,%7}, {%8,%9}, {%0,%1,%2,%3};"
                 : "+f"(c[0]), "+f"(c[1]), "+f"(c[2]), "+f"(c[3])
                 : "r"(a[0]), "r"(a[1]), "r"(a[2]), "r"(a[3]), "r"(b0), "r"(b1));
}
__device__ __forceinline__ uint32_t pack2(float a, float b) {
    __nv_bfloat16 h0 = __float2bfloat16(a), h1 = __float2bfloat16(b);
    return (uint32_t)__bfloat16_as_ushort(h0) | ((uint32_t)__bfloat16_as_ushort(h1) << 16);
}
#define MBAR_INIT(a, c) asm volatile("mbarrier.init.shared.b64 [%0], %1;" :: "r"(a), "r"((uint32_t)(c)) : "memory")
#define MBAR_EXPECT_TX(a, tx) asm volatile("mbarrier.arrive.expect_tx.shared.b64 _, [%0], %1;" :: "r"(a), "r"((uint32_t)(tx)) : "memory")
#define MBAR_ARRIVE(a) asm volatile("mbarrier.arrive.shared.b64 _, [%0];" :: "r"(a) : "memory")
#define MBAR_WAIT(a, ph) do { \
    uint32_t _m = (a); uint32_t _p = (uint32_t)(ph); uint32_t _d; \
    asm volatile("{\n\t.reg .pred p;\n\tmbarrier.try_wait.parity.acquire.cta.shared::cta.b64 p, [%1], %2;\n\tselp.b32 %0,1,0,p;\n\t}" \
        : "=r"(_d) : "r"(_m), "r"(_p) : "memory"); \
    if (!_d) { \
        asm volatile("{\n\t.reg .pred P1;\n\tWL_%=:\n\tmbarrier.try_wait.parity.acquire.cta.shared::cta.b64 P1, [%0], %1, 0x989680;\n\t@P1 bra.uni WD_%=;\n\tbra.uni WL_%=;\n\tWD_%=:\n\t}" \
            :: "r"(_m), "r"(_p) : "memory"); \
    } } while (0)
__device__ __forceinline__ void bulk_g2s(uint32_t dst, const void* src, uint32_t bytes, uint32_t mbar) {
    asm volatile("cp.async.bulk.shared::cta.global.mbarrier::complete_tx::bytes [%0], [%1], %2, [%3];"
                 :: "r"(dst), "l"(src), "r"(bytes), "r"(mbar) : "memory");
}

// pack 8 floats -> 16B hi plane + 16B lo plane
__device__ __forceinline__ void split8(const float* v, uint4& hi, uint4& lo) {
    uint32_t h[4], l[4];
#pragma unroll
    for (int i = 0; i < 4; i++) {
        __nv_bfloat16 a = __float2bfloat16(v[2*i]), b = __float2bfloat16(v[2*i+1]);
        h[i] = (uint32_t)__bfloat16_as_ushort(a) | ((uint32_t)__bfloat16_as_ushort(b) << 16);
        l[i] = pack2(v[2*i] - __bfloat162float(a), v[2*i+1] - __bfloat162float(b));
    }
    hi = make_uint4(h[0], h[1], h[2], h[3]);
    lo = make_uint4(l[0], l[1], l[2], l[3]);
}

// ---------------------------------------------------------------------------
// Kernel 0: zero output + reset counters
// ---------------------------------------------------------------------------
__global__ void zero_kernel(float4* __restrict__ out) {
    int i = blockIdx.x * blockDim.x + threadIdx.x;
    out[i] = make_float4(0.f, 0.f, 0.f, 0.f);
    if (blockIdx.x == 0 && threadIdx.x < EE) g_cnt[threadIdx.x] = 0;
}

// ---------------------------------------------------------------------------
// Kernel 1: router (fp32, validated)
// ---------------------------------------------------------------------------
__global__ __launch_bounds__(256) void router_kernel(const float* __restrict__ x,
                                                     const float* __restrict__ rw) {
    int n = blockIdx.x, tid = threadIdx.x;
    const float* xr = x + (size_t)n * DD;
    float acc[EE];
#pragma unroll
    for (int e = 0; e < EE; e++) acc[e] = 0.f;
    for (int i = tid; i < DD; i += 256) {
        float xv = xr[i];
#pragma unroll
        for (int e = 0; e < EE; e++) acc[e] += xv * rw[e * DD + i];
    }
#pragma unroll
    for (int e = 0; e < EE; e++)
#pragma unroll
        for (int o = 16; o > 0; o >>= 1) acc[e] += __shfl_down_sync(0xffffffffu, acc[e], o);

    __shared__ float sm[8][EE];
    int warp = tid >> 5, lane = tid & 31;
    if (lane == 0)
#pragma unroll
        for (int e = 0; e < EE; e++) sm[warp][e] = acc[e];
    __syncthreads();

    if (tid == 0) {
        float logits[EE];
#pragma unroll
        for (int e = 0; e < EE; e++) {
            float s = 0.f;
#pragma unroll
            for (int w = 0; w < 8; w++) s += sm[w][e];
            logits[e] = s;
        }
        int i0 = 0; float v0 = logits[0];
#pragma unroll
        for (int e = 1; e < EE; e++) if (logits[e] > v0) { v0 = logits[e]; i0 = e; }
        int i1 = 0; float v1 = -3.0e38f;
#pragma unroll
        for (int e = 0; e < EE; e++) if (e != i0 && logits[e] > v1) { v1 = logits[e]; i1 = e; }
        float ex = __expf(v1 - v0);
        float g0 = 1.f / (1.f + ex);
        float g1 = ex * g0;
        int p0 = atomicAdd(&g_cnt[i0], 1);
        g_tok[i0 * NN + p0] = n;  g_gate[i0 * NN + p0] = g0;
        int p1 = atomicAdd(&g_cnt[i1], 1);
        g_tok[i1 * NN + p1] = n;  g_gate[i1 * NN + p1] = g1;
    }
}

// ---------------------------------------------------------------------------
// Kernel 2: gather tokens, split hi/lo into swizzled tiled A planes
// ---------------------------------------------------------------------------
__global__ __launch_bounds__(128) void gather_kernel(const float* __restrict__ x) {
    int e = blockIdx.y, slot = blockIdx.x;
    int cnt = g_cnt[e];
    int pad = (cnt + 127) & ~127;  if (pad > NN) pad = NN;
    if (slot >= pad) return;
    int mb = slot >> 7, m = slot & 127;
    int t = threadIdx.x;
    int kc = t >> 2, u = t & 3;
    size_t plane = (((size_t)e * 64 + mb) * 32 + kc) * 8192;
    uint32_t off = (uint32_t)m * 64 + (uint32_t)((u ^ ((m >> 1) & 3)) << 4);
    uint8_t* dh = (uint8_t*)g_xg_hi + plane + off;
    uint8_t* dl = (uint8_t*)g_xg_lo + plane + off;
    if (slot < cnt) {
        int tok = g_tok[e * NN + slot];
        const float4* xs = (const float4*)(x + (size_t)tok * DD + t * 8);
        float v[8];
        float4 a = xs[0], b = xs[1];
        v[0]=a.x; v[1]=a.y; v[2]=a.z; v[3]=a.w; v[4]=b.x; v[5]=b.y; v[6]=b.z; v[7]=b.w;
        uint4 hi, lo;
        split8(v, hi, lo);
        *(uint4*)dh = hi;
        *(uint4*)dl = lo;
    } else {
        uint4 z = make_uint4(0,0,0,0);
        *(uint4*)dh = z;
        *(uint4*)dl = z;
    }
}

// ---------------------------------------------------------------------------
// Kernels 3/4: weights -> transposed, split, swizzled tiled B planes
// ---------------------------------------------------------------------------
template<int R, int C, int WHICH>
__global__ __launch_bounds__(256) void wsplit_kernel(const float* __restrict__ w) {
    int kc = blockIdx.x, nb = blockIdx.y, e = blockIdx.z;
    const float* src = w + (size_t)e * R * C;
    int t = threadIdx.x;
    int n = nb * 256 + t;
    float vals[32];
#pragma unroll
    for (int j = 0; j < 32; j++)
        vals[j] = src[(size_t)(kc * 32 + j) * C + n];
    __nv_bfloat16* hi = (WHICH == 0) ? g_w1t_hi : g_w2t_hi;
    __nv_bfloat16* lo = (WHICH == 0) ? g_w1t_lo : g_w2t_lo;
    size_t plane = (((size_t)e * (C / 256) + nb) * (R / 32) + kc) * 16384;
    int sw = (t >> 1) & 3;
    uint32_t rbase = (uint32_t)t * 64;
#pragma unroll
    for (int u = 0; u < 4; u++) {
        uint4 h4, l4;
        split8(vals + u * 8, h4, l4);
        uint32_t off = rbase + (uint32_t)((u ^ sw) << 4);
        *(uint4*)((uint8_t*)hi + plane + off) = h4;
        *(uint4*)((uint8_t*)lo + plane + off) = l4;
    }
}

// ---------------------------------------------------------------------------
// bulk-fed mma.sync grouped GEMM with producer/consumer mbarrier dataflow.
// D[128x256] += A * B^T, bf16 hi/lo 3-pass. 512 threads (16 warps, 4Mx4N).
// full[s]: tx-tracked load completion; empty[s]: 16 per-warp read-done arrivals.
// ---------------------------------------------------------------------------
template<int KTOT, int KSLICES, bool IS_G1>
__global__ __launch_bounds__(512, 1) void gemm_mma(float* __restrict__ out) {
    constexpr int KCA = KTOT / 32;
    constexpr int KC  = (KTOT / KSLICES) / TK;
    constexpr int NB  = (IS_G1 ? HH : DD) / TN;
    int zz = blockIdx.z;
    int e = zz & (EE - 1);
    int slice = zz >> 3;
    int kc0 = slice * KC;
    int cnt = g_cnt[e];
    int m0  = blockIdx.y * TM;
    if (m0 >= cnt) return;
    int mb  = blockIdx.y;
    int nb  = blockIdx.x;
    int n0  = nb * TN;

    extern __shared__ char smem[];
    uint32_t sb = smem_u32(smem);
    uint32_t fullb  = sb + 4 * STAGE_BYTES;        // 4 x 8B
    uint32_t emptyb = fullb + 32;                  // 4 x 8B

    const uint8_t *pAh, *pAl, *pBh, *pBl;
    {
        size_t ap = (((size_t)e * 64 + mb) * KCA) * 8192;
        size_t bp = (((size_t)e * NB + nb) * KCA) * 16384;
        if (IS_G1) {
            pAh = (const uint8_t*)g_xg_hi + ap;  pAl = (const uint8_t*)g_xg_lo + ap;
            pBh = (const uint8_t*)g_w1t_hi + bp; pBl = (const uint8_t*)g_w1t_lo + bp;
        } else {
            pAh = (const uint8_t*)g_h_hi + ap;   pAl = (const uint8_t*)g_h_lo + ap;
            pBh = (const uint8_t*)g_w2t_hi + bp; pBl = (const uint8_t*)g_w2t_lo + bp;
        }
    }

    int tid = threadIdx.x;
    if (tid == 0) {
#pragma unroll
        for (int s = 0; s < 4; s++) {
            MBAR_INIT(fullb + s * 8, 1);
            MBAR_INIT(emptyb + s * 8, 16);
        }
    }
    __syncthreads();

    auto issue = [&](int j) {
        int s = j & 3;
        uint32_t st = sb + (uint32_t)s * STAGE_BYTES;
        uint32_t mb_s = fullb + s * 8;
        size_t kc = (size_t)(kc0 + j);
        MBAR_EXPECT_TX(mb_s, STAGE_BYTES);
        bulk_g2s(st,        pAh + kc * 8192, 8192, mb_s);
        bulk_g2s(st + A_LO, pAl + kc * 8192, 8192, mb_s);
        bulk_g2s(st + B_HI, pBh + kc * 16384, 16384, mb_s);
        bulk_g2s(st + B_LO, pBl + kc * 16384, 16384, mb_s);
    };
    if (tid == 0) {
#pragma unroll
        for (int j0 = 0; j0 < 4; j0++) if (j0 < KC) issue(j0);
    }

    // ---- warp / lane geometry ----
    int wid = tid >> 5, lane = tid & 31;
    int wm = wid & 3;
    int wn = wid >> 2;
    int li = lane >> 3;
    int lr = lane & 7;
    int kadd = li >> 1;
    int rsel = (li & 1) * 8 + lr;

    uint32_t abase[2]; int asw[2];
#pragma unroll
    for (int mt = 0; mt < 2; mt++) {
        int m = wm * 32 + mt * 16 + rsel;
        abase[mt] = (uint32_t)m * 64;
        asw[mt] = (m >> 1) & 3;
    }
    uint32_t bbase[4]; int bsw[4];
#pragma unroll
    for (int p = 0; p < 4; p++) {
        int n = wn * 64 + p * 16 + rsel;
        bbase[p] = (uint32_t)n * 64;
        bsw[p] = (n >> 1) & 3;
    }

    float acc[2][8][4];
#pragma unroll
    for (int a = 0; a < 2; a++)
#pragma unroll
        for (int b = 0; b < 8; b++)
#pragma unroll
            for (int c = 0; c < 4; c++) acc[a][b][c] = 0.f;

    for (int j = 0; j < KC; j++) {
        int s = j & 3;
        uint32_t ph = (j >> 2) & 1;
        MBAR_WAIT(fullb + s * 8, ph);
        uint32_t st = sb + (uint32_t)s * STAGE_BYTES;
#pragma unroll
        for (int kq = 0; kq < 4; kq += 2) {
            uint32_t ahi[2][4], alo[2][4];
#pragma unroll
            for (int mt = 0; mt < 2; mt++) {
                uint32_t off = abase[mt] + (uint32_t)((((kq + kadd) ^ asw[mt])) << 4);
                ldsm4(ahi[mt], st + off);
                ldsm4(alo[mt], st + A_LO + off);
            }
#pragma unroll
            for (int p = 0; p < 4; p++) {
                uint32_t bh[4], bl[4];
                uint32_t off = bbase[p] + (uint32_t)((((kq + kadd) ^ bsw[p])) << 4);
                ldsm4(bh, st + B_HI + off);
                ldsm4(bl, st + B_LO + off);
#pragma unroll
                for (int mt = 0; mt < 2; mt++) {
#pragma unroll
                    for (int sgl = 0; sgl < 2; sgl++) {
                        float* c = acc[mt][p * 2 + sgl];
                        mma16816(c, ahi[mt], bh[sgl], bh[2 + sgl]);
                        mma16816(c, ahi[mt], bl[sgl], bl[2 + sgl]);
                        mma16816(c, alo[mt], bh[sgl], bh[2 + sgl]);
                    }
                }
            }
        }
        // this warp is done reading stage s (ldmatrix is warp-synchronous)
        if (lane == 0) MBAR_ARRIVE(emptyb + s * 8);
        // producer: re-issue stage s for chunk j+4 once ALL warps released it
        if (tid == 0 && j + 4 < KC) {
            MBAR_WAIT(emptyb + s * 8, ph);
            issue(j + 4);
        }
    }

    // ---- epilogue ----
    int r4 = lane >> 2, cpair = (lane & 3) * 2;
    if (IS_G1) {
        size_t planeH0 = (((size_t)e * 64 + mb) * 64) * 8192;
#pragma unroll
        for (int mt = 0; mt < 2; mt++) {
#pragma unroll
            for (int q = 0; q < 8; q++) {
                int kcH = (n0 >> 5) + wn * 2 + (q >> 2);
                int u = q & 3;
#pragma unroll
                for (int half = 0; half < 2; half++) {
                    int lm = wm * 32 + mt * 16 + r4 + half * 8;
                    float v0 = acc[mt][q][half * 2 + 0];
                    float v1 = acc[mt][q][half * 2 + 1];
                    v0 = fmaxf(v0, 0.f); v0 *= v0;
                    v1 = fmaxf(v1, 0.f); v1 *= v1;
                    __nv_bfloat16 h0 = __float2bfloat16(v0), h1 = __float2bfloat16(v1);
                    uint32_t hw = (uint32_t)__bfloat16_as_ushort(h0) |
                                  ((uint32_t)__bfloat16_as_ushort(h1) << 16);
                    uint32_t lw = pack2(v0 - __bfloat162float(h0), v1 - __bfloat162float(h1));
                    size_t off = planeH0 + (size_t)kcH * 8192 +
                                 (uint32_t)(lm * 64 + ((u ^ ((lm >> 1) & 3)) << 4) + cpair * 2);
                    *(uint32_t*)((uint8_t*)g_h_hi + off) = hw;
                    *(uint32_t*)((uint8_t*)g_h_lo + off) = lw;
                }
            }
        }
    } else {
#pragma unroll
        for (int mt = 0; mt < 2; mt++) {
            int gm = m0 + wm * 32 + mt * 16;
            int   tokh[2];
            float gth[2];
#pragma unroll
            for (int half = 0; half < 2; half++) {
                int slot = gm + r4 + half * 8;
                bool ok = slot < cnt;
                tokh[half] = ok ? g_tok[e * NN + slot] : -1;
                gth[half]  = ok ? g_gate[e * NN + slot] : 0.f;
            }
#pragma unroll
            for (int q = 0; q < 8; q++) {
                int gn = n0 + wn * 64 + q * 8 + cpair;
#pragma unroll
                for (int half = 0; half < 2; half++) {
                    if (tokh[half] >= 0) {
                        float* orow = out + (size_t)tokh[half] * DD + gn;
                        atomicAdd(orow,     gth[half] * acc[mt][q][half * 2 + 0]);
                        atomicAdd(orow + 1, gth[half] * acc[mt][q][half * 2 + 1]);
                    }
                }
            }
        }
    }
}

// ---------------------------------------------------------------------------
extern "C" void kernel_launch(void* const* d_in, const int* in_sizes, int n_in,
                              void* d_out, int out_size) {
    const float* x  = (const float*)d_in[0];   // (B,T,D)
    const float* rw = (const float*)d_in[1];   // (E,D)
    const float* w1 = (const float*)d_in[2];   // (E,D,H)
    const float* w2 = (const float*)d_in[3];   // (E,H,D)
    float* out = (float*)d_out;                // (B,T,D) fp32

    cudaFuncSetAttribute(gemm_mma<DD, 1, true>,  cudaFuncAttributeMaxDynamicSharedMemorySize, SMEM_BYTES);
    cudaFuncSetAttribute(gemm_mma<HH, 2, false>, cudaFuncAttributeMaxDynamicSharedMemorySize, SMEM_BYTES);

    int zblocks = out_size / (4 * 256);
    zero_kernel<<<zblocks, 256>>>((float4*)out);
    router_kernel<<<NN, 256>>>(x, rw);
    wsplit_kernel<DD, HH, 0><<<dim3(DD / 32, HH / 256, EE), 256>>>(w1);
    wsplit_kernel<HH, DD, 1><<<dim3(HH / 32, DD / 256, EE), 256>>>(w2);
    gather_kernel<<<dim3(NN, EE), 128>>>(x);
    gemm_mma<DD, 1, true><<<dim3(HH / TN, NN / TM, EE), 512, SMEM_BYTES>>>(nullptr);
    gemm_mma<HH, 2, false><<<dim3(DD / TN, NN / TM, EE * 2), 512, SMEM_BYTES>>>(out);
}